// round 4
// baseline (speedup 1.0000x reference)
#include <cuda_runtime.h>

#define BB 4
#define IC 256
#define NN 4096
#define HW 16384

// ---- scratch (device globals; no allocation allowed) ----
__device__ float g_TH[BB*IC*NN];   // theta  [b][o][n]
__device__ float g_PH[BB*IC*NN];   // phi    [b][o][n]
__device__ float g_GX[BB*NN*IC];   // g      [b][n][o]
__device__ float g_YS[BB*NN*IC];   // y_s    [b][n][o]
__device__ float g_FC[BB*IC*IC];   // f_c    [b][c][d]
__device__ float g_YC[BB*NN*IC];   // y_c    [b][n][d]
__device__ float g_Z [BB*64*HW];   // z      [b][c][h][w]
__device__ float g_H [BB*16*HW];   // hmid

// ============================================================
// proj: out[o][n] = sum_i W[o][i] * X[i][n] + bias[o]
// mode 0 -> g_TH ([o][n]); 1 -> g_PH ([o][n]); 2 -> g_GX ([n][o])
// grid (64 ntiles, 4 otiles, 4 b), 256 threads, 64x64 tile, 4x4 micro
// ============================================================
__global__ __launch_bounds__(256) void proj_kernel(
    const float* __restrict__ x, const float* __restrict__ W,
    const float* __restrict__ bias, int mode)
{
    __shared__ __align__(16) float sA[64][33];
    __shared__ __align__(16) float sB[32][68];
    const int n0 = blockIdx.x*64, o0 = blockIdx.y*64, b = blockIdx.z;
    const float* X = x + b*IC*NN;
    const int tid = threadIdx.x, tx = tid & 15, ty = tid >> 4;
    float acc[4][4] = {};
    for (int k0 = 0; k0 < IC; k0 += 32) {
        #pragma unroll
        for (int l = 0; l < 8; l++) {
            int idx = l*256 + tid;
            int oi = idx >> 5, ki = idx & 31;
            sA[oi][ki] = W[(o0+oi)*IC + k0 + ki];
        }
        #pragma unroll
        for (int l = 0; l < 8; l++) {
            int idx = l*256 + tid;
            int ki = idx >> 6, ni = idx & 63;
            sB[ki][ni] = X[(size_t)(k0+ki)*NN + n0 + ni];
        }
        __syncthreads();
        #pragma unroll
        for (int k = 0; k < 32; k++) {
            float a[4];
            #pragma unroll
            for (int i = 0; i < 4; i++) a[i] = sA[4*ty+i][k];
            float4 bv = *(const float4*)&sB[k][4*tx];
            float bb[4] = {bv.x, bv.y, bv.z, bv.w};
            #pragma unroll
            for (int i = 0; i < 4; i++)
                #pragma unroll
                for (int j = 0; j < 4; j++)
                    acc[i][j] += a[i]*bb[j];
        }
        __syncthreads();
    }
    float* dst = (mode == 0) ? g_TH : (mode == 1) ? g_PH : g_GX;
    #pragma unroll
    for (int i = 0; i < 4; i++) {
        int o = o0 + 4*ty + i;
        float bi = bias[o];
        #pragma unroll
        for (int j = 0; j < 4; j++) {
            int n = n0 + 4*tx + j;
            float v = acc[i][j] + bi;
            if (mode == 2) dst[((size_t)b*NN + n)*IC + o] = v;
            else           dst[((size_t)b*IC + o)*NN + n] = v;
        }
    }
}

// ============================================================
// spatial attention (streaming softmax, no max-rescale needed:
// logits bounded ~ +-9 by construction)
// grid (64 qtiles, 4 b), 256 threads
// ============================================================
__global__ __launch_bounds__(256) void attn_kernel()
{
    __shared__ __align__(16) float sA[64][68]; // Q chunk, then P tile
    __shared__ __align__(16) float sB[64][68]; // K chunk, then V chunk
    __shared__ float sL[64];
    const int b = blockIdx.y, q0 = blockIdx.x*64;
    const int tid = threadIdx.x, tx = tid & 15, ty = tid >> 4;
    const float* TH = g_TH + (size_t)b*IC*NN;
    const float* PH = g_PH + (size_t)b*IC*NN;
    const float* GX = g_GX + (size_t)b*NN*IC;
    float acc[4][4][4] = {};   // [ochunk][qi][oj]
    if (tid < 64) sL[tid] = 0.f;

    for (int m0 = 0; m0 < NN; m0 += 64) {
        float s[4][4] = {};
        #pragma unroll 1
        for (int kc = 0; kc < 4; kc++) {
            #pragma unroll
            for (int l = 0; l < 16; l++) {
                int idx = l*256 + tid;
                int ki = idx >> 6, qi = idx & 63;
                sA[ki][qi] = TH[(size_t)(kc*64+ki)*NN + q0 + qi];
                sB[ki][qi] = PH[(size_t)(kc*64+ki)*NN + m0 + qi];
            }
            __syncthreads();
            #pragma unroll
            for (int k = 0; k < 64; k++) {
                float4 av = *(const float4*)&sA[k][4*ty];
                float4 bv = *(const float4*)&sB[k][4*tx];
                float a[4] = {av.x, av.y, av.z, av.w};
                float bq[4] = {bv.x, bv.y, bv.z, bv.w};
                #pragma unroll
                for (int i = 0; i < 4; i++)
                    #pragma unroll
                    for (int j = 0; j < 4; j++)
                        s[i][j] += a[i]*bq[j];
            }
            __syncthreads();
        }
        // P = exp(S) into sA
        #pragma unroll
        for (int i = 0; i < 4; i++) {
            float4 pv;
            pv.x = __expf(s[i][0]); pv.y = __expf(s[i][1]);
            pv.z = __expf(s[i][2]); pv.w = __expf(s[i][3]);
            *(float4*)&sA[4*ty+i][4*tx] = pv;
        }
        __syncthreads();
        if (tid < 64) {
            float r = 0.f;
            #pragma unroll
            for (int m = 0; m < 64; m++) r += sA[tid][m];
            sL[tid] += r;
        }
        // O += P @ V
        #pragma unroll 1
        for (int oc = 0; oc < 4; oc++) {
            #pragma unroll
            for (int l = 0; l < 16; l++) {
                int idx = l*256 + tid;
                int mi = idx >> 6, oi = idx & 63;
                sB[mi][oi] = GX[(size_t)(m0+mi)*IC + oc*64 + oi];
            }
            __syncthreads();
            #pragma unroll
            for (int m = 0; m < 64; m++) {
                float4 vv = *(const float4*)&sB[m][4*tx];
                float vq[4] = {vv.x, vv.y, vv.z, vv.w};
                float p[4];
                #pragma unroll
                for (int i = 0; i < 4; i++) p[i] = sA[4*ty+i][m];
                #pragma unroll
                for (int i = 0; i < 4; i++)
                    #pragma unroll
                    for (int j = 0; j < 4; j++)
                        acc[oc][i][j] += p[i]*vq[j];
            }
            __syncthreads();
        }
    }
    float* YS = g_YS + (size_t)b*NN*IC;
    #pragma unroll
    for (int i = 0; i < 4; i++) {
        float inv = 1.0f / sL[4*ty+i];
        #pragma unroll
        for (int oc = 0; oc < 4; oc++) {
            float4 w4;
            w4.x = acc[oc][i][0]*inv; w4.y = acc[oc][i][1]*inv;
            w4.z = acc[oc][i][2]*inv; w4.w = acc[oc][i][3]*inv;
            *(float4*)&YS[(size_t)(q0+4*ty+i)*IC + oc*64 + 4*tx] = w4;
        }
    }
}

// ============================================================
// f_c[c][d] = sum_n TH[c][n]*PH[d][n]  (grid (8,8,4), 32x32 tile)
// ============================================================
__global__ __launch_bounds__(256) void fcgemm_kernel()
{
    __shared__ __align__(16) float sA[32][68], sB[32][68];
    const int c0 = blockIdx.x*32, d0 = blockIdx.y*32, b = blockIdx.z;
    const int tid = threadIdx.x, tx = tid & 15, ty = tid >> 4;
    const float* TH = g_TH + (size_t)b*IC*NN;
    const float* PH = g_PH + (size_t)b*IC*NN;
    float acc[2][2] = {};
    for (int n0 = 0; n0 < NN; n0 += 64) {
        #pragma unroll
        for (int l = 0; l < 8; l++) {
            int idx = l*256 + tid;
            int ci = idx >> 6, ni = idx & 63;
            sA[ci][ni] = TH[(size_t)(c0+ci)*NN + n0 + ni];
            sB[ci][ni] = PH[(size_t)(d0+ci)*NN + n0 + ni];
        }
        __syncthreads();
        #pragma unroll
        for (int k = 0; k < 64; k += 4) {
            float4 a0 = *(const float4*)&sA[2*ty  ][k];
            float4 a1 = *(const float4*)&sA[2*ty+1][k];
            float4 b0 = *(const float4*)&sB[2*tx  ][k];
            float4 b1 = *(const float4*)&sB[2*tx+1][k];
            acc[0][0] += a0.x*b0.x + a0.y*b0.y + a0.z*b0.z + a0.w*b0.w;
            acc[0][1] += a0.x*b1.x + a0.y*b1.y + a0.z*b1.z + a0.w*b1.w;
            acc[1][0] += a1.x*b0.x + a1.y*b0.y + a1.z*b0.z + a1.w*b0.w;
            acc[1][1] += a1.x*b1.x + a1.y*b1.y + a1.z*b1.z + a1.w*b1.w;
        }
        __syncthreads();
    }
    float* FC = g_FC + (size_t)b*IC*IC;
    #pragma unroll
    for (int i = 0; i < 2; i++)
        #pragma unroll
        for (int j = 0; j < 2; j++)
            FC[(c0+2*ty+i)*IC + d0+2*tx+j] = acc[i][j];
}

// softmax over d, per (b,c) row; grid (256,4), 256 threads
__global__ __launch_bounds__(256) void fcsoftmax_kernel()
{
    __shared__ float red[256];
    const int b = blockIdx.y, c = blockIdx.x, tid = threadIdx.x;
    float* row = g_FC + ((size_t)b*IC + c)*IC;
    float v = row[tid];
    red[tid] = v; __syncthreads();
    for (int s = 128; s > 0; s >>= 1) {
        if (tid < s) red[tid] = fmaxf(red[tid], red[tid+s]);
        __syncthreads();
    }
    float m = red[0]; __syncthreads();
    float e = __expf(v - m);
    red[tid] = e; __syncthreads();
    for (int s = 128; s > 0; s >>= 1) {
        if (tid < s) red[tid] += red[tid+s];
        __syncthreads();
    }
    row[tid] = e / red[0];
}

// y_c[n][d] = sum_o GX[n][o]*FC[o][d]; grid (64,4,4), 64x64 tile
__global__ __launch_bounds__(256) void ycgemm_kernel()
{
    __shared__ __align__(16) float sA[64][33];
    __shared__ __align__(16) float sB[32][68];
    const int n0 = blockIdx.x*64, d0 = blockIdx.y*64, b = blockIdx.z;
    const int tid = threadIdx.x, tx = tid & 15, ty = tid >> 4;
    const float* GX = g_GX + (size_t)b*NN*IC;
    const float* FC = g_FC + (size_t)b*IC*IC;
    float acc[4][4] = {};
    for (int k0 = 0; k0 < IC; k0 += 32) {
        #pragma unroll
        for (int l = 0; l < 8; l++) {
            int idx = l*256 + tid;
            int ni = idx >> 5, ki = idx & 31;
            sA[ni][ki] = GX[(size_t)(n0+ni)*IC + k0 + ki];
        }
        #pragma unroll
        for (int l = 0; l < 8; l++) {
            int idx = l*256 + tid;
            int ki = idx >> 6, di = idx & 63;
            sB[ki][di] = FC[(k0+ki)*IC + d0 + di];
        }
        __syncthreads();
        #pragma unroll
        for (int k = 0; k < 32; k++) {
            float a[4];
            #pragma unroll
            for (int i = 0; i < 4; i++) a[i] = sA[4*ty+i][k];
            float4 bv = *(const float4*)&sB[k][4*tx];
            float bq[4] = {bv.x, bv.y, bv.z, bv.w};
            #pragma unroll
            for (int i = 0; i < 4; i++)
                #pragma unroll
                for (int j = 0; j < 4; j++)
                    acc[i][j] += a[i]*bq[j];
        }
        __syncthreads();
    }
    float* YC = g_YC + (size_t)b*NN*IC;
    #pragma unroll
    for (int i = 0; i < 4; i++)
        #pragma unroll
        for (int j = 0; j < 4; j++)
            YC[(size_t)(n0+4*ty+i)*IC + d0+4*tx+j] = acc[i][j];
}

// ============================================================
// z = x + gs*(Ws@ys + Ws_b) + gc*(Wc@yc + Wc_b); writes g_Z and d_out z-part
// grid (256 pixel-tiles, 4 b), 256 threads (tx=pixel 0..63, ty=oc group 0..3)
// ============================================================
__global__ __launch_bounds__(256) void zmix_kernel(
    const float* __restrict__ x,
    const float* __restrict__ Ws_w, const float* __restrict__ Ws_b,
    const float* __restrict__ Wc_w, const float* __restrict__ Wc_b,
    const float* __restrict__ gs, const float* __restrict__ gc,
    float* __restrict__ zout)
{
    __shared__ float sW[64][64];
    __shared__ float sD[64][65];
    const int b = blockIdx.y, p0 = blockIdx.x*64;
    const int tid = threadIdx.x, tx = tid & 63, ty = tid >> 6;
    float accs[16] = {}, accc[16] = {};

    // phase 1: spatial branch (ys gather: o = 4i + h/32, n = (h%32)*128 + w)
    #pragma unroll
    for (int l = 0; l < 16; l++) {
        int idx = l*256 + tid;
        sW[idx >> 6][idx & 63] = Ws_w[idx];
        int i = idx >> 6, px = idx & 63;
        int p = p0 + px, h = p >> 7, w = p & 127;
        int o = 4*i + (h >> 5), n = ((h & 31) << 7) | w;
        sD[i][px] = g_YS[((size_t)(b << 12) + n)*IC + o];
    }
    __syncthreads();
    #pragma unroll 4
    for (int i = 0; i < 64; i++) {
        float yv = sD[i][tx];
        #pragma unroll
        for (int k = 0; k < 16; k++) accs[k] += sW[16*ty+k][i]*yv;
    }
    __syncthreads();
    // phase 2: channel branch (yc gather: n = 64i + h/2, d = (h%2)*128 + w)
    #pragma unroll
    for (int l = 0; l < 16; l++) {
        int idx = l*256 + tid;
        sW[idx >> 6][idx & 63] = Wc_w[idx];
        int i = idx >> 6, px = idx & 63;
        int p = p0 + px, h = p >> 7, w = p & 127;
        int n = (i << 6) + (h >> 1), d = ((h & 1) << 7) | w;
        sD[i][px] = g_YC[((size_t)(b << 12) + n)*IC + d];
    }
    __syncthreads();
    #pragma unroll 4
    for (int i = 0; i < 64; i++) {
        float cv = sD[i][tx];
        #pragma unroll
        for (int k = 0; k < 16; k++) accc[k] += sW[16*ty+k][i]*cv;
    }
    float gsv = gs[0], gcv = gc[0];
    int p = p0 + tx;
    #pragma unroll
    for (int k = 0; k < 16; k++) {
        int oc = 16*ty + k;
        size_t idx = (size_t)(b*64 + oc)*HW + p;
        float z = x[idx] + gsv*(accs[k] + Ws_b[oc]) + gcv*(accc[k] + Wc_b[oc]);
        g_Z[idx] = z;
        zout[idx] = z;
    }
}

// conv3x3 64->16 + relu; grid (4 wt, 16 ht, 4 b), block (32,8)
__global__ __launch_bounds__(256) void conv1_kernel(
    const float* __restrict__ m1w, const float* __restrict__ m1b)
{
    __shared__ float sw[16*64*9];
    __shared__ float st[10][36];
    const int b = blockIdx.z, h0 = blockIdx.y*8, w0 = blockIdx.x*32;
    const int tx = threadIdx.x, ty = threadIdx.y;
    const int tid = ty*32 + tx;
    for (int i = tid; i < 9216; i += 256) sw[i] = m1w[i];
    float acc[16];
    #pragma unroll
    for (int oc = 0; oc < 16; oc++) acc[oc] = m1b[oc];
    for (int ic = 0; ic < 64; ic++) {
        const float* zp = g_Z + (size_t)(b*64 + ic)*HW;
        __syncthreads();
        for (int l = tid; l < 340; l += 256) {
            int yy = l / 34, xx = l % 34;
            int hh = h0 - 1 + yy, ww = w0 - 1 + xx;
            st[yy][xx] = (hh >= 0 && hh < 128 && ww >= 0 && ww < 128)
                         ? zp[hh*128 + ww] : 0.f;
        }
        __syncthreads();
        #pragma unroll
        for (int dy = 0; dy < 3; dy++)
            #pragma unroll
            for (int dx = 0; dx < 3; dx++) {
                float zv = st[ty+dy][tx+dx];
                #pragma unroll
                for (int oc = 0; oc < 16; oc++)
                    acc[oc] += sw[(oc*64 + ic)*9 + dy*3 + dx]*zv;
            }
    }
    int h = h0 + ty, w = w0 + tx;
    #pragma unroll
    for (int oc = 0; oc < 16; oc++)
        g_H[(size_t)(b*16 + oc)*HW + h*128 + w] = fmaxf(acc[oc], 0.f);
}

// conv3x3 16->1; grid (4,16,4), block (32,8); writes logit part of d_out
__global__ __launch_bounds__(256) void conv2_kernel(
    const float* __restrict__ m2w, const float* __restrict__ m2b,
    float* __restrict__ out)
{
    __shared__ float sw[144];
    __shared__ float st[10][36];
    const int b = blockIdx.z, h0 = blockIdx.y*8, w0 = blockIdx.x*32;
    const int tx = threadIdx.x, ty = threadIdx.y;
    const int tid = ty*32 + tx;
    if (tid < 144) sw[tid] = m2w[tid];
    float acc = m2b[0];
    for (int ic = 0; ic < 16; ic++) {
        const float* hp = g_H + (size_t)(b*16 + ic)*HW;
        __syncthreads();
        for (int l = tid; l < 340; l += 256) {
            int yy = l / 34, xx = l % 34;
            int hh = h0 - 1 + yy, ww = w0 - 1 + xx;
            st[yy][xx] = (hh >= 0 && hh < 128 && ww >= 0 && ww < 128)
                         ? hp[hh*128 + ww] : 0.f;
        }
        __syncthreads();
        #pragma unroll
        for (int dy = 0; dy < 3; dy++)
            #pragma unroll
            for (int dx = 0; dx < 3; dx++)
                acc += sw[ic*9 + dy*3 + dx]*st[ty+dy][tx+dx];
    }
    out[(size_t)b*HW + (h0+ty)*128 + (w0+tx)] = acc;
}

extern "C" void kernel_launch(void* const* d_in, const int* in_sizes, int n_in,
                              void* d_out, int out_size)
{
    const float* x    = (const float*)d_in[0];
    const float* g_w  = (const float*)d_in[1];
    const float* g_b  = (const float*)d_in[2];
    const float* th_w = (const float*)d_in[3];
    const float* th_b = (const float*)d_in[4];
    const float* ph_w = (const float*)d_in[5];
    const float* ph_b = (const float*)d_in[6];
    const float* Ws_w = (const float*)d_in[7];
    const float* Ws_b = (const float*)d_in[8];
    const float* Wc_w = (const float*)d_in[9];
    const float* Wc_b = (const float*)d_in[10];
    const float* gs   = (const float*)d_in[11];
    const float* gc   = (const float*)d_in[12];
    const float* m1w  = (const float*)d_in[13];
    const float* m1b  = (const float*)d_in[14];
    const float* m2w  = (const float*)d_in[15];
    const float* m2b  = (const float*)d_in[16];
    float* out = (float*)d_out;              // logit [4*16384] then z [4*64*16384]

    dim3 gproj(64, 4, 4);
    proj_kernel<<<gproj, 256>>>(x, th_w, th_b, 0);
    proj_kernel<<<gproj, 256>>>(x, ph_w, ph_b, 1);
    proj_kernel<<<gproj, 256>>>(x, g_w,  g_b,  2);

    fcgemm_kernel<<<dim3(8, 8, 4), 256>>>();
    fcsoftmax_kernel<<<dim3(256, 4), 256>>>();

    attn_kernel<<<dim3(64, 4), 256>>>();

    ycgemm_kernel<<<dim3(64, 4, 4), 256>>>();

    zmix_kernel<<<dim3(256, 4), 256>>>(x, Ws_w, Ws_b, Wc_w, Wc_b, gs, gc,
                                       out + 65536);

    conv1_kernel<<<dim3(4, 16, 4), dim3(32, 8)>>>(m1w, m1b);
    conv2_kernel<<<dim3(4, 16, 4), dim3(32, 8)>>>(m2w, m2b, out);
}

// round 6
// speedup vs baseline: 2.9421x; 2.9421x over previous
#include <cuda_runtime.h>
#include <cstdint>

#define BB 4
#define IC 256
#define NN 4096
#define HW 16384

// ---- scratch ----
__device__ __align__(16) float g_XT[BB*NN*IC];        // x^T [b][n][c]
__device__ __align__(16) float g_TH[BB*NN*IC];        // theta [b][n][c]
__device__ __align__(16) float g_PH[BB*NN*IC];        // phi   [b][n][c]
__device__ __align__(16) float g_GX[BB*IC*NN];        // g     [b][o][n]
__device__ __align__(16) float g_P [(size_t)BB*NN*NN];// exp(S) [b][n][m]
__device__ __align__(16) float g_Lp[BB*32*NN];        // row-sum partials
__device__ __align__(16) float g_Li[BB*NN];           // 1/rowsum
__device__ __align__(16) float g_YS[BB*NN*IC];        // y_s [b][n][o]
__device__ __align__(16) float g_FCP[BB*8*IC*IC];
__device__ __align__(16) float g_FC[BB*IC*IC];
__device__ __align__(16) float g_YC[BB*NN*IC];        // y_c [b][n][d]
__device__ __align__(16) float g_Z [BB*64*HW];
__device__ __align__(16) float g_H [BB*16*HW];

static __device__ __forceinline__ uint32_t f2tf(float f) {
    uint32_t u; asm("cvt.rna.tf32.f32 %0, %1;" : "=r"(u) : "f"(f)); return u;
}
static __device__ __forceinline__ void mma8(float* d, const uint32_t* a, const uint32_t* b) {
    asm volatile(
        "mma.sync.aligned.m16n8k8.row.col.f32.tf32.tf32.f32 "
        "{%0,%1,%2,%3}, {%4,%5,%6,%7}, {%8,%9}, {%0,%1,%2,%3};"
        : "+f"(d[0]), "+f"(d[1]), "+f"(d[2]), "+f"(d[3])
        : "r"(a[0]), "r"(a[1]), "r"(a[2]), "r"(a[3]), "r"(b[0]), "r"(b[1]));
}

// ============================================================
// warp-MMA tf32 GEMM: D[bx*128..][by*128..] = A @ B^T (+epilogue)
// A [M rows][K] ldA (K-major), B [N rows][K] ldB (K-major), K%32==0
// 8 warps: wm=wid&3 (32 rows), wn=wid>>2 (64 cols); warp tile 32x64
// mode 0: +aux[col]; 1: +aux[row]; 2: exp + row partsums->aux2; 3: *aux[b*NN+row]
// ============================================================
__global__ __launch_bounds__(256, 2) void wgemm(
    const float* __restrict__ A, int ldA, size_t Abs,
    const float* __restrict__ B, int ldB, size_t Bbs,
    float* __restrict__ D, int ldD, size_t Dbs,
    int K, const float* __restrict__ aux, float* __restrict__ aux2, int mode)
{
    __shared__ uint32_t sA[128][36];
    __shared__ uint32_t sB[128][36];
    __shared__ float sred[2][128];
    const int tid = threadIdx.x;
    const int wid = tid >> 5, lane = tid & 31;
    const int gid = lane >> 2, tig = lane & 3;
    const int wm = wid & 3, wn = wid >> 2;
    const float* At = A + (size_t)blockIdx.z*Abs + (size_t)blockIdx.x*128*ldA;
    const float* Bt = B + (size_t)blockIdx.z*Bbs + (size_t)blockIdx.y*128*ldB;

    float acc[2][8][4] = {};

    for (int k0 = 0; k0 < K; k0 += 32) {
        #pragma unroll
        for (int l = 0; l < 4; l++) {
            int f = l*256 + tid, r = f >> 3, c4 = (f & 7)*4;
            float4 va = *(const float4*)(At + (size_t)r*ldA + k0 + c4);
            float4 vb = *(const float4*)(Bt + (size_t)r*ldB + k0 + c4);
            sA[r][c4+0] = f2tf(va.x); sA[r][c4+1] = f2tf(va.y);
            sA[r][c4+2] = f2tf(va.z); sA[r][c4+3] = f2tf(va.w);
            sB[r][c4+0] = f2tf(vb.x); sB[r][c4+1] = f2tf(vb.y);
            sB[r][c4+2] = f2tf(vb.z); sB[r][c4+3] = f2tf(vb.w);
        }
        __syncthreads();
        #pragma unroll
        for (int ks = 0; ks < 4; ks++) {
            const int kk = ks*8;
            uint32_t af[2][4], bf[8][2];
            #pragma unroll
            for (int i = 0; i < 2; i++) {
                int rb = wm*32 + i*16;
                af[i][0] = sA[rb + gid    ][kk + tig];
                af[i][1] = sA[rb + 8 + gid][kk + tig];
                af[i][2] = sA[rb + gid    ][kk + tig + 4];
                af[i][3] = sA[rb + 8 + gid][kk + tig + 4];
            }
            #pragma unroll
            for (int j = 0; j < 8; j++) {
                int nb = wn*64 + j*8 + gid;
                bf[j][0] = sB[nb][kk + tig];
                bf[j][1] = sB[nb][kk + tig + 4];
            }
            #pragma unroll
            for (int i = 0; i < 2; i++)
                #pragma unroll
                for (int j = 0; j < 8; j++)
                    mma8(acc[i][j], af[i], bf[j]);
        }
        __syncthreads();
    }

    // ---- epilogue ----
    float* Dt = D + (size_t)blockIdx.z*Dbs + (size_t)blockIdx.x*128*ldD + blockIdx.y*128;
    #pragma unroll
    for (int i = 0; i < 2; i++) {
        const int r0 = wm*32 + i*16 + gid, r1 = r0 + 8;
        const int rg0 = blockIdx.x*128 + r0, rg1 = rg0 + 8;
        float add0 = 0.f, add1 = 0.f, mul0 = 1.f, mul1 = 1.f;
        if (mode == 1) { add0 = aux[rg0]; add1 = aux[rg1]; }
        if (mode == 3) {
            mul0 = aux[(size_t)blockIdx.z*NN + rg0];
            mul1 = aux[(size_t)blockIdx.z*NN + rg1];
        }
        float ls0 = 0.f, ls1 = 0.f;
        #pragma unroll
        for (int j = 0; j < 8; j++) {
            const int cl = wn*64 + j*8 + 2*tig;
            float v0 = acc[i][j][0], v1 = acc[i][j][1];
            float v2 = acc[i][j][2], v3 = acc[i][j][3];
            if (mode == 0) {
                const int cg = blockIdx.y*128 + cl;
                float a0 = __ldg(&aux[cg]), a1 = __ldg(&aux[cg+1]);
                v0 += a0; v1 += a1; v2 += a0; v3 += a1;
            } else if (mode == 1) {
                v0 += add0; v1 += add0; v2 += add1; v3 += add1;
            } else if (mode == 2) {
                v0 = __expf(v0); v1 = __expf(v1);
                v2 = __expf(v2); v3 = __expf(v3);
                ls0 += v0 + v1; ls1 += v2 + v3;
            } else {
                v0 *= mul0; v1 *= mul0; v2 *= mul1; v3 *= mul1;
            }
            *(float2*)(Dt + (size_t)r0*ldD + cl) = make_float2(v0, v1);
            *(float2*)(Dt + (size_t)r1*ldD + cl) = make_float2(v2, v3);
        }
        if (mode == 2) {
            ls0 += __shfl_xor_sync(0xffffffffu, ls0, 1);
            ls0 += __shfl_xor_sync(0xffffffffu, ls0, 2);
            ls1 += __shfl_xor_sync(0xffffffffu, ls1, 1);
            ls1 += __shfl_xor_sync(0xffffffffu, ls1, 2);
            if (tig == 0) { sred[wn][r0] = ls0; sred[wn][r1] = ls1; }
        }
    }
    if (mode == 2) {
        __syncthreads();
        if (tid < 128)
            aux2[((size_t)blockIdx.z*gridDim.y + blockIdx.y)*NN + blockIdx.x*128 + tid]
                = sred[0][tid] + sred[1][tid];
    }
}

// x[b][c][n] -> g_XT[b][n][c]; grid (128, 8, 4), block (32,8)
__global__ __launch_bounds__(256) void transpose_kernel(const float* __restrict__ x)
{
    __shared__ float t[32][33];
    const int b = blockIdx.z, n0 = blockIdx.x*32, c0 = blockIdx.y*32;
    const int tx = threadIdx.x, ty = threadIdx.y;
    #pragma unroll
    for (int i = 0; i < 4; i++)
        t[ty + i*8][tx] = x[(size_t)b*IC*NN + (size_t)(c0 + ty + i*8)*NN + n0 + tx];
    __syncthreads();
    #pragma unroll
    for (int i = 0; i < 4; i++)
        g_XT[(size_t)b*NN*IC + (size_t)(n0 + ty + i*8)*IC + c0 + tx] = t[tx][ty + i*8];
}

// g_Li[b][n] = 1 / sum_{mt<32} g_Lp[b][mt][n]; grid (16,4), 256 thr
__global__ __launch_bounds__(256) void lreduce_kernel()
{
    const int b = blockIdx.y, n = blockIdx.x*256 + threadIdx.x;
    float s = 0.f;
    #pragma unroll
    for (int mt = 0; mt < 32; mt++) s += g_Lp[((size_t)b*32 + mt)*NN + n];
    g_Li[(size_t)b*NN + n] = 1.0f / s;
}

// f_c partials, split-K x8: grid (4,4,32=b*8+ks), 64x64 tile
__global__ __launch_bounds__(256) void fcgemm_kernel()
{
    __shared__ __align__(16) float sA[32][68], sB[32][68];
    const int c0 = blockIdx.x*64, d0 = blockIdx.y*64;
    const int bz = blockIdx.z, b = bz >> 3, ks = bz & 7;
    const int tid = threadIdx.x, tx = tid & 15, ty = tid >> 4;
    const float* TH = g_TH + (size_t)b*NN*IC + (size_t)ks*512*IC;
    const float* PH = g_PH + (size_t)b*NN*IC + (size_t)ks*512*IC;
    float acc[4][4] = {};
    for (int n0 = 0; n0 < 512; n0 += 32) {
        #pragma unroll
        for (int l = 0; l < 8; l++) {
            int idx = l*256 + tid, ki = idx >> 6, ci = idx & 63;
            sA[ki][ci] = TH[(size_t)(n0 + ki)*IC + c0 + ci];
            sB[ki][ci] = PH[(size_t)(n0 + ki)*IC + d0 + ci];
        }
        __syncthreads();
        #pragma unroll
        for (int k = 0; k < 32; k++) {
            float a[4];
            #pragma unroll
            for (int i = 0; i < 4; i++) a[i] = sA[k][4*ty + i];
            float4 bv = *(const float4*)&sB[k][4*tx];
            float bb[4] = {bv.x, bv.y, bv.z, bv.w};
            #pragma unroll
            for (int i = 0; i < 4; i++)
                #pragma unroll
                for (int j = 0; j < 4; j++) acc[i][j] += a[i]*bb[j];
        }
        __syncthreads();
    }
    float* FCP = g_FCP + (size_t)bz*IC*IC;
    #pragma unroll
    for (int i = 0; i < 4; i++)
        #pragma unroll
        for (int j = 0; j < 4; j++)
            FCP[(c0 + 4*ty + i)*IC + d0 + 4*tx + j] = acc[i][j];
}

// reduce split-K + softmax over d; grid (256,4), 256 thr
__global__ __launch_bounds__(256) void fcsoftmax_kernel()
{
    __shared__ float red[256];
    const int b = blockIdx.y, c = blockIdx.x, tid = threadIdx.x;
    float v = 0.f;
    #pragma unroll
    for (int ks = 0; ks < 8; ks++)
        v += g_FCP[(((size_t)b*8 + ks)*IC + c)*IC + tid];
    red[tid] = v; __syncthreads();
    for (int s = 128; s > 0; s >>= 1) {
        if (tid < s) red[tid] = fmaxf(red[tid], red[tid + s]);
        __syncthreads();
    }
    float m = red[0]; __syncthreads();
    float e = __expf(v - m);
    red[tid] = e; __syncthreads();
    for (int s = 128; s > 0; s >>= 1) {
        if (tid < s) red[tid] += red[tid + s];
        __syncthreads();
    }
    g_FC[((size_t)b*IC + c)*IC + tid] = e / red[0];
}

// y_c[n][d] = sum_o GX[o][n]*FC[o][d]; grid (64,4,4), 64x64 tile
__global__ __launch_bounds__(256) void ycgemm_kernel()
{
    __shared__ __align__(16) float sA[32][68], sB[32][68];
    const int n0 = blockIdx.x*64, d0 = blockIdx.y*64, b = blockIdx.z;
    const int tid = threadIdx.x, tx = tid & 15, ty = tid >> 4;
    const float* GX = g_GX + (size_t)b*IC*NN;
    const float* FC = g_FC + (size_t)b*IC*IC;
    float acc[4][4] = {};
    for (int k0 = 0; k0 < IC; k0 += 32) {
        #pragma unroll
        for (int l = 0; l < 8; l++) {
            int idx = l*256 + tid, ki = idx >> 6, ni = idx & 63;
            sA[ki][ni] = GX[(size_t)(k0 + ki)*NN + n0 + ni];
            sB[ki][ni] = FC[(k0 + ki)*IC + d0 + ni];
        }
        __syncthreads();
        #pragma unroll
        for (int k = 0; k < 32; k++) {
            float a[4];
            #pragma unroll
            for (int i = 0; i < 4; i++) a[i] = sA[k][4*ty + i];
            float4 bv = *(const float4*)&sB[k][4*tx];
            float bb[4] = {bv.x, bv.y, bv.z, bv.w};
            #pragma unroll
            for (int i = 0; i < 4; i++)
                #pragma unroll
                for (int j = 0; j < 4; j++) acc[i][j] += a[i]*bb[j];
        }
        __syncthreads();
    }
    float* YC = g_YC + (size_t)b*NN*IC;
    #pragma unroll
    for (int i = 0; i < 4; i++)
        #pragma unroll
        for (int j = 0; j < 4; j++)
            YC[(size_t)(n0 + 4*ty + i)*IC + d0 + 4*tx + j] = acc[i][j];
}

// z = x + gs*(Ws@ys+b) + gc*(Wc@yc+b); grid (256,4), 256 thr
__global__ __launch_bounds__(256) void zmix_kernel(
    const float* __restrict__ x,
    const float* __restrict__ Ws_w, const float* __restrict__ Ws_b,
    const float* __restrict__ Wc_w, const float* __restrict__ Wc_b,
    const float* __restrict__ gs, const float* __restrict__ gc,
    float* __restrict__ zout)
{
    __shared__ float sW[64][64];
    __shared__ float sD[64][65];
    const int b = blockIdx.y, p0 = blockIdx.x*64;
    const int tid = threadIdx.x, tx = tid & 63, ty = tid >> 6;
    float accs[16] = {}, accc[16] = {};
    #pragma unroll
    for (int l = 0; l < 16; l++) {
        int idx = l*256 + tid;
        sW[idx >> 6][idx & 63] = Ws_w[idx];
        int i = idx >> 6, px = idx & 63;
        int p = p0 + px, h = p >> 7, w = p & 127;
        int o = 4*i + (h >> 5), n = ((h & 31) << 7) | w;
        sD[i][px] = g_YS[((size_t)(b << 12) + n)*IC + o];
    }
    __syncthreads();
    #pragma unroll 4
    for (int i = 0; i < 64; i++) {
        float yv = sD[i][tx];
        #pragma unroll
        for (int k = 0; k < 16; k++) accs[k] += sW[16*ty + k][i]*yv;
    }
    __syncthreads();
    #pragma unroll
    for (int l = 0; l < 16; l++) {
        int idx = l*256 + tid;
        sW[idx >> 6][idx & 63] = Wc_w[idx];
        int i = idx >> 6, px = idx & 63;
        int p = p0 + px, h = p >> 7, w = p & 127;
        int n = (i << 6) + (h >> 1), d = ((h & 1) << 7) | w;
        sD[i][px] = g_YC[((size_t)(b << 12) + n)*IC + d];
    }
    __syncthreads();
    #pragma unroll 4
    for (int i = 0; i < 64; i++) {
        float cv = sD[i][tx];
        #pragma unroll
        for (int k = 0; k < 16; k++) accc[k] += sW[16*ty + k][i]*cv;
    }
    float gsv = gs[0], gcv = gc[0];
    int p = p0 + tx;
    #pragma unroll
    for (int k = 0; k < 16; k++) {
        int oc = 16*ty + k;
        size_t idx = (size_t)(b*64 + oc)*HW + p;
        float z = x[idx] + gsv*(accs[k] + Ws_b[oc]) + gcv*(accc[k] + Wc_b[oc]);
        g_Z[idx] = z;
        zout[idx] = z;
    }
}

// conv3x3 64->16 + relu; grid (4,16,4), block (32,8)
__global__ __launch_bounds__(256) void conv1_kernel(
    const float* __restrict__ m1w, const float* __restrict__ m1b)
{
    __shared__ float sw[16*64*9];
    __shared__ float st[10][36];
    const int b = blockIdx.z, h0 = blockIdx.y*8, w0 = blockIdx.x*32;
    const int tx = threadIdx.x, ty = threadIdx.y, tid = ty*32 + tx;
    for (int i = tid; i < 9216; i += 256) sw[i] = m1w[i];
    float acc[16];
    #pragma unroll
    for (int oc = 0; oc < 16; oc++) acc[oc] = m1b[oc];
    for (int ic = 0; ic < 64; ic++) {
        const float* zp = g_Z + (size_t)(b*64 + ic)*HW;
        __syncthreads();
        for (int l = tid; l < 340; l += 256) {
            int yy = l / 34, xx = l % 34;
            int hh = h0 - 1 + yy, ww = w0 - 1 + xx;
            st[yy][xx] = (hh >= 0 && hh < 128 && ww >= 0 && ww < 128) ? zp[hh*128 + ww] : 0.f;
        }
        __syncthreads();
        #pragma unroll
        for (int dy = 0; dy < 3; dy++)
            #pragma unroll
            for (int dx = 0; dx < 3; dx++) {
                float zv = st[ty + dy][tx + dx];
                #pragma unroll
                for (int oc = 0; oc < 16; oc++)
                    acc[oc] += sw[(oc*64 + ic)*9 + dy*3 + dx]*zv;
            }
    }
    int h = h0 + ty, w = w0 + tx;
    #pragma unroll
    for (int oc = 0; oc < 16; oc++)
        g_H[(size_t)(b*16 + oc)*HW + h*128 + w] = fmaxf(acc[oc], 0.f);
}

// conv3x3 16->1; grid (4,16,4), block (32,8)
__global__ __launch_bounds__(256) void conv2_kernel(
    const float* __restrict__ m2w, const float* __restrict__ m2b,
    float* __restrict__ out)
{
    __shared__ float sw[144];
    __shared__ float st[10][36];
    const int b = blockIdx.z, h0 = blockIdx.y*8, w0 = blockIdx.x*32;
    const int tx = threadIdx.x, ty = threadIdx.y, tid = ty*32 + tx;
    if (tid < 144) sw[tid] = m2w[tid];
    float acc = m2b[0];
    for (int ic = 0; ic < 16; ic++) {
        const float* hp = g_H + (size_t)(b*16 + ic)*HW;
        __syncthreads();
        for (int l = tid; l < 340; l += 256) {
            int yy = l / 34, xx = l % 34;
            int hh = h0 - 1 + yy, ww = w0 - 1 + xx;
            st[yy][xx] = (hh >= 0 && hh < 128 && ww >= 0 && ww < 128) ? hp[hh*128 + ww] : 0.f;
        }
        __syncthreads();
        #pragma unroll
        for (int dy = 0; dy < 3; dy++)
            #pragma unroll
            for (int dx = 0; dx < 3; dx++)
                acc += sw[ic*9 + dy*3 + dx]*st[ty + dy][tx + dx];
    }
    out[(size_t)b*HW + (h0 + ty)*128 + (w0 + tx)] = acc;
}

extern "C" void kernel_launch(void* const* d_in, const int* in_sizes, int n_in,
                              void* d_out, int out_size)
{
    const float* x    = (const float*)d_in[0];
    const float* g_w  = (const float*)d_in[1];
    const float* g_b  = (const float*)d_in[2];
    const float* th_w = (const float*)d_in[3];
    const float* th_b = (const float*)d_in[4];
    const float* ph_w = (const float*)d_in[5];
    const float* ph_b = (const float*)d_in[6];
    const float* Ws_w = (const float*)d_in[7];
    const float* Ws_b = (const float*)d_in[8];
    const float* Wc_w = (const float*)d_in[9];
    const float* Wc_b = (const float*)d_in[10];
    const float* gs   = (const float*)d_in[11];
    const float* gc   = (const float*)d_in[12];
    const float* m1w  = (const float*)d_in[13];
    const float* m1b  = (const float*)d_in[14];
    const float* m2w  = (const float*)d_in[15];
    const float* m2b  = (const float*)d_in[16];
    float* out = (float*)d_out;   // logit [4*16384] then z [4*64*16384]

    float *XT, *TH, *PH, *GX, *P, *Lp, *Li, *YS;
    cudaGetSymbolAddress((void**)&XT, g_XT);
    cudaGetSymbolAddress((void**)&TH, g_TH);
    cudaGetSymbolAddress((void**)&PH, g_PH);
    cudaGetSymbolAddress((void**)&GX, g_GX);
    cudaGetSymbolAddress((void**)&P,  g_P);
    cudaGetSymbolAddress((void**)&Lp, g_Lp);
    cudaGetSymbolAddress((void**)&Li, g_Li);
    cudaGetSymbolAddress((void**)&YS, g_YS);

    transpose_kernel<<<dim3(128, 8, 4), dim3(32, 8)>>>(x);

    // theta: D[n][c] = XT @ th_w^T  (M=4096, N=256)
    wgemm<<<dim3(32, 2, 4), 256>>>(XT, IC, (size_t)NN*IC,
        th_w, IC, 0, TH, IC, (size_t)NN*IC, IC, th_b, nullptr, 0);
    // phi
    wgemm<<<dim3(32, 2, 4), 256>>>(XT, IC, (size_t)NN*IC,
        ph_w, IC, 0, PH, IC, (size_t)NN*IC, IC, ph_b, nullptr, 0);
    // g: D[o][n] = g_w @ XT^T  (M=256, N=4096)
    wgemm<<<dim3(2, 32, 4), 256>>>(g_w, IC, 0,
        XT, IC, (size_t)NN*IC, GX, NN, (size_t)IC*NN, IC, g_b, nullptr, 1);

    fcgemm_kernel<<<dim3(4, 4, 32), 256>>>();
    fcsoftmax_kernel<<<dim3(256, 4), 256>>>();

    // P = exp(TH @ PH^T) + row partial sums  (M=N=4096)
    wgemm<<<dim3(32, 32, 4), 256>>>(TH, IC, (size_t)NN*IC,
        PH, IC, (size_t)NN*IC, P, NN, (size_t)NN*NN, IC, nullptr, Lp, 2);
    lreduce_kernel<<<dim3(16, 4), 256>>>();
    // y_s[n][o] = (P @ GX^T) * Li[n]  (M=4096, N=256, K=4096)
    wgemm<<<dim3(32, 2, 4), 256>>>(P, NN, (size_t)NN*NN,
        GX, NN, (size_t)IC*NN, YS, IC, (size_t)NN*IC, NN, Li, nullptr, 3);

    ycgemm_kernel<<<dim3(64, 4, 4), 256>>>();
    zmix_kernel<<<dim3(256, 4), 256>>>(x, Ws_w, Ws_b, Wc_w, Wc_b, gs, gc, out + 65536);
    conv1_kernel<<<dim3(4, 16, 4), dim3(32, 8)>>>(m1w, m1b);
    conv2_kernel<<<dim3(4, 16, 4), dim3(32, 8)>>>(m2w, m2b, out);
}